// round 14
// baseline (speedup 1.0000x reference)
#include <cuda_runtime.h>
#include <cuda.h>
#include <cuda_bf16.h>
#include <cstdint>

// Problem constants
#define PB   256      // batch
#define PE   512      // embed dim
#define PC   8192     // classes
#define PK   10       // centers per class
#define PN   (PC*PK)  // 81920 rows of fc
#define LMD        10.0f
#define INV_GAMMA  10.0f
#define TAU        0.2f
#define MARGIN     0.01f

// Scratch (static device globals; no allocation allowed)
__device__ __nv_bfloat16 g_ebf[(size_t)PB * PE];   // emb bf16
__device__ float g_h[(size_t)PB * PC];             // soft-pooled class similarity
__device__ float g_regpart[PC];                    // per-class regularizer partial
__device__ float g_rowloss[PB];                    // per-batch-row CE loss
__device__ int   g_ctr = 0;                        // completion counter (self-resetting)

// ---------------------------------------------------------------------------
// PTX helpers
// ---------------------------------------------------------------------------
__device__ __forceinline__ uint32_t smem_u32(const void* p) {
    return (uint32_t)__cvta_generic_to_shared(p);
}
#define MBAR_INIT(a, n) \
    asm volatile("mbarrier.init.shared.b64 [%0], %1;" :: "r"(a), "r"(n) : "memory")
#define MBAR_EXPECT_TX(a, b) \
    asm volatile("mbarrier.arrive.expect_tx.shared.b64 _, [%0], %1;" :: "r"(a), "r"(b) : "memory")
__device__ __forceinline__ void mbar_wait(uint32_t mbar, uint32_t parity) {
    uint32_t done = 0;
    while (!done) {
        asm volatile(
            "{\n\t.reg .pred p;\n\t"
            "mbarrier.try_wait.parity.acquire.cta.shared::cta.b64 p, [%1], %2, 0x989680;\n\t"
            "selp.b32 %0, 1, 0, p;\n\t}"
            : "=r"(done) : "r"(mbar), "r"(parity) : "memory");
    }
}
#define TMA_LOAD_2D(smem, map, cx, cy, mbar) \
    asm volatile("cp.async.bulk.tensor.2d.shared::cta.global.tile.mbarrier::complete_tx::bytes " \
                 "[%0], [%1, {%2, %3}], [%4];" \
                 :: "r"(smem), "l"(map), "r"(cx), "r"(cy), "r"(mbar) : "memory")
#define FENCE_PROXY_ASYNC() asm volatile("fence.proxy.async.shared::cta;" ::: "memory")

__device__ __forceinline__ void ldsm_x4(uint32_t& r0, uint32_t& r1, uint32_t& r2, uint32_t& r3, uint32_t addr) {
    asm volatile("ldmatrix.sync.aligned.m8n8.x4.shared.b16 {%0,%1,%2,%3}, [%4];\n"
                 : "=r"(r0), "=r"(r1), "=r"(r2), "=r"(r3) : "r"(addr));
}
__device__ __forceinline__ void ldsm_x2(uint32_t& r0, uint32_t& r1, uint32_t addr) {
    asm volatile("ldmatrix.sync.aligned.m8n8.x2.shared.b16 {%0,%1}, [%2];\n"
                 : "=r"(r0), "=r"(r1) : "r"(addr));
}
__device__ __forceinline__ void mma16816(float* c, const uint32_t* a, const uint32_t* b) {
    asm volatile("mma.sync.aligned.m16n8k16.row.col.f32.bf16.bf16.f32 "
                 "{%0,%1,%2,%3}, {%4,%5,%6,%7}, {%8,%9}, {%0,%1,%2,%3};\n"
                 : "+f"(c[0]), "+f"(c[1]), "+f"(c[2]), "+f"(c[3])
                 : "r"(a[0]), "r"(a[1]), "r"(a[2]), "r"(a[3]), "r"(b[0]), "r"(b[1]));
}

// ---------------------------------------------------------------------------
// Kernel 0: emb -> bf16 (tiny)
// ---------------------------------------------------------------------------
__global__ __launch_bounds__(256) void k_prep(const float* __restrict__ emb)
{
    const int i = blockIdx.x * 256 + threadIdx.x;
    g_ebf[i] = __float2bfloat16(emb[i]);
}

// ---------------------------------------------------------------------------
// Kernel 1: GEMM x = e @ fc.T with normalization FUSED (scale-after-
// accumulate): B path streams fc fp32 via TMA, converts to bf16 in-place,
// accumulates per-row sum-of-squares in registers across all K-stages, and
// the epilogue divides x (and the fused gram) by the row norms.
// Block 128(m) x 80(n); KSTAGE=64, 8 stages, 3-slot ring; occupancy 2.
// Grid (2 m-tiles fast, 1024 n-tiles slow) so the m-pair sharing a B tile is
// co-resident -> fc fp32 read dedupes in L2.
// ---------------------------------------------------------------------------
#define KSTAGE 64
#define NSTAGE (PE / KSTAGE)            // 8
#define NSLOT 3
#define NBLK  80
#define A_BYTES (128 * 128)             // 16384 (bf16 A tile, SW128 TMA)
#define BF_BYTES (NBLK * 256)           // 20480 (fp32 B staging; bf16 tile in-place at front)
#define STG_BYTES (A_BYTES + BF_BYTES)  // 36864
#define GSMEM (NSLOT * STG_BYTES + 1024)  // 111616

__global__ __launch_bounds__(256, 2) void k_gemm_mma(
    const __grid_constant__ CUtensorMap tma_a,
    const __grid_constant__ CUtensorMap tma_b)
{
    extern __shared__ char dsm_raw[];
    char* dsm = (char*)(((uintptr_t)dsm_raw + 1023) & ~(uintptr_t)1023);
    const uint32_t dsm_u = smem_u32(dsm);

    __shared__ uint64_t s_mbar[NSLOT];
    __shared__ float inv_s[NBLK];

    const int tid    = threadIdx.x;
    const int lane   = tid & 31;
    const int warp   = tid >> 5;
    const int warp_m = warp >> 1;      // 0..3
    const int warp_n = warp & 1;       // 0..1
    const int m0     = blockIdx.x * 128;     // m-tile = fast dim (2)
    const int n0     = blockIdx.y * NBLK;    // n-tile = slow dim (1024)
    const bool do_gram = (blockIdx.x == 0);

    const uint32_t mb0 = smem_u32(&s_mbar[0]);

    if (tid == 0) {
#pragma unroll
        for (int s = 0; s < NSLOT; s++) MBAR_INIT(mb0 + 8 * s, 1);
    }
    __syncthreads();
    if (tid == 0) {
        FENCE_PROXY_ASYNC();
#pragma unroll
        for (int s = 0; s < NSLOT; s++) {
            MBAR_EXPECT_TX(mb0 + 8 * s, STG_BYTES);
            TMA_LOAD_2D(dsm_u + s * STG_BYTES,           &tma_a, s * KSTAGE, m0, mb0 + 8 * s);
            TMA_LOAD_2D(dsm_u + s * STG_BYTES + A_BYTES, &tma_b, s * KSTAGE, n0, mb0 + 8 * s);
        }
    }

    float acc[2][5][4];
#pragma unroll
    for (int i = 0; i < 2; i++)
#pragma unroll
        for (int j = 0; j < 5; j++)
#pragma unroll
            for (int r = 0; r < 4; r++) acc[i][j][r] = 0.f;

    // gram accumulators (m-tile 0 blocks): warp w owns class w of this n-block
    float ga0[4] = {0.f, 0.f, 0.f, 0.f};
    float ga1[4] = {0.f, 0.f, 0.f, 0.f};
    const int wbase = warp * 10;
    const int g_ar  = (lane & 15) < 10 ? (lane & 15) : 9;
    const int g_br  = lane & 7;
    const int g_br2 = g_br < 2 ? g_br : 1;

    // per-row sum-of-squares partials (warp w rows w*10..w*10+9, lane = 2 cols)
    float ssr[10];
#pragma unroll
    for (int r = 0; r < 10; r++) ssr[r] = 0.f;

    const int a_r  = lane & 15, a_sel = lane >> 4;
    const int b_r  = lane & 7,  b_sel = (lane >> 3) & 1;
    const int cvt_ci  = lane >> 2;   // 16B chunk for bf16 write
    const int cvt_sub = lane & 3;    // word within chunk

    uint32_t af[2][2][4];
    uint32_t bfr[2][5][2];
    float2 cv[10];                   // conversion staging (phase1 -> phase2)

    int ph[NSLOT] = {0, 0, 0};

    // ---- prologue: convert slot 0 (fp32 -> bf16 in place, 2-phase) ----
    mbar_wait(mb0 + 0, 0); ph[0] = 1;
    {
        const char* fp = dsm + A_BYTES;
#pragma unroll
        for (int r = 0; r < 10; r++) {
            cv[r] = *reinterpret_cast<const float2*>(fp + (wbase + r) * 256 + lane * 8);
            ssr[r] += cv[r].x * cv[r].x + cv[r].y * cv[r].y;
        }
        __syncthreads();
        char* bp = dsm + A_BYTES;
#pragma unroll
        for (int r = 0; r < 10; r++) {
            const int row = wbase + r;
            __nv_bfloat162 p = __floats2bfloat162_rn(cv[r].x, cv[r].y);
            *reinterpret_cast<uint32_t*>(bp + row * 128 + ((cvt_ci ^ (row & 7)) << 4) + cvt_sub * 4)
                = *reinterpret_cast<uint32_t*>(&p);
        }
        __syncthreads();
    }

    for (int t = 0; t < NSTAGE; t++) {
        const int s = t % NSLOT;
        const uint32_t aBase = dsm_u + s * STG_BYTES;
        const uint32_t bBase = aBase + A_BYTES;

        // prime fragments for ks=0
        {
#pragma unroll
            for (int jn = 0; jn < 5; jn++) {
                const int row = warp_n * 40 + jn * 8 + b_r;
                ldsm_x2(bfr[0][jn][0], bfr[0][jn][1],
                        bBase + row * 128 + ((b_sel ^ (row & 7)) << 4));
            }
#pragma unroll
            for (int mi = 0; mi < 2; mi++) {
                const int row = warp_m * 32 + mi * 16 + a_r;
                ldsm_x4(af[0][mi][0], af[0][mi][1], af[0][mi][2], af[0][mi][3],
                        aBase + row * 128 + ((a_sel ^ (row & 7)) << 4));
            }
        }
#pragma unroll
        for (int ks = 0; ks < 4; ks++) {
            const int cur = ks & 1, nxt = cur ^ 1;
            if (ks < 3) {
#pragma unroll
                for (int jn = 0; jn < 5; jn++) {
                    const int row = warp_n * 40 + jn * 8 + b_r;
                    const int ci  = (ks + 1) * 2 + b_sel;
                    ldsm_x2(bfr[nxt][jn][0], bfr[nxt][jn][1],
                            bBase + row * 128 + ((ci ^ (row & 7)) << 4));
                }
#pragma unroll
                for (int mi = 0; mi < 2; mi++) {
                    const int row = warp_m * 32 + mi * 16 + a_r;
                    const int ci  = (ks + 1) * 2 + a_sel;
                    ldsm_x4(af[nxt][mi][0], af[nxt][mi][1], af[nxt][mi][2], af[nxt][mi][3],
                            aBase + row * 128 + ((ci ^ (row & 7)) << 4));
                }
            }
#pragma unroll
            for (int mi = 0; mi < 2; mi++)
#pragma unroll
                for (int jn = 0; jn < 5; jn++)
                    mma16816(acc[mi][jn], af[cur][mi], bfr[cur][jn]);
        }

        // fused gram on this stage's bf16 tile (unnormalized fc)
        if (do_gram) {
#pragma unroll
            for (int ks = 0; ks < 4; ks++) {
                uint32_t a[4], b0[2], b1[2];
                const int rowA  = wbase + g_ar;
                const int rowB0 = wbase + g_br;
                const int rowB1 = wbase + 8 + g_br2;
                const int ciA = ks * 2 + a_sel;
                const int ciB = ks * 2 + b_sel;
                ldsm_x4(a[0], a[1], a[2], a[3],
                        bBase + rowA * 128 + ((ciA ^ (rowA & 7)) << 4));
                ldsm_x2(b0[0], b0[1],
                        bBase + rowB0 * 128 + ((ciB ^ (rowB0 & 7)) << 4));
                ldsm_x2(b1[0], b1[1],
                        bBase + rowB1 * 128 + ((ciB ^ (rowB1 & 7)) << 4));
                mma16816(ga0, a, b0);
                mma16816(ga1, a, b1);
            }
        }

        // convert next stage's B tile (phase 1: fp32 -> regs + ss accumulate)
        const int sn = (t + 1) % NSLOT;
        if (t + 1 < NSTAGE) {
            mbar_wait(mb0 + 8 * sn, ph[sn]); ph[sn] ^= 1;
            const char* fp = dsm + sn * STG_BYTES + A_BYTES;
#pragma unroll
            for (int r = 0; r < 10; r++) {
                cv[r] = *reinterpret_cast<const float2*>(fp + (wbase + r) * 256 + lane * 8);
                ssr[r] += cv[r].x * cv[r].x + cv[r].y * cv[r].y;
            }
        }
        __syncthreads();
        if (t + 1 < NSTAGE) {   // phase 2: write bf16 (in place)
            char* bp = dsm + sn * STG_BYTES + A_BYTES;
#pragma unroll
            for (int r = 0; r < 10; r++) {
                const int row = wbase + r;
                __nv_bfloat162 p = __floats2bfloat162_rn(cv[r].x, cv[r].y);
                *reinterpret_cast<uint32_t*>(bp + row * 128 + ((cvt_ci ^ (row & 7)) << 4) + cvt_sub * 4)
                    = *reinterpret_cast<uint32_t*>(&p);
            }
        }
        __syncthreads();
        if (tid == 0 && t + NSLOT < NSTAGE) {
            MBAR_EXPECT_TX(mb0 + 8 * s, STG_BYTES);
            TMA_LOAD_2D(dsm_u + s * STG_BYTES,           &tma_a, (t + NSLOT) * KSTAGE, m0, mb0 + 8 * s);
            TMA_LOAD_2D(dsm_u + s * STG_BYTES + A_BYTES, &tma_b, (t + NSLOT) * KSTAGE, n0, mb0 + 8 * s);
        }
    }

    // ---- row norms: reduce ss across lanes, publish inverse norms ----
#pragma unroll
    for (int r = 0; r < 10; r++) {
        float v = ssr[r];
#pragma unroll
        for (int o = 16; o; o >>= 1) v += __shfl_xor_sync(0xffffffffu, v, o);
        if (lane == 0) inv_s[wbase + r] = 1.0f / fmaxf(sqrtf(v), 1e-12f);
    }
    __syncthreads();

    // ---- gram epilogue: scale by inv_i*inv_j, extract upper triangle ----
    if (do_gram) {
        const int g = lane >> 2, t2 = lane & 3;
        float racc = 0.f;
        const float gv[8] = {ga0[0], ga0[1], ga0[2], ga0[3], ga1[0], ga1[1], ga1[2], ga1[3]};
        const int rr[8]   = {g, g, g + 8, g + 8, g, g, g + 8, g + 8};
        const int cc[8]   = {2 * t2, 2 * t2 + 1, 2 * t2, 2 * t2 + 1,
                             8 + 2 * t2, 8 + 2 * t2 + 1, 8 + 2 * t2, 8 + 2 * t2 + 1};
#pragma unroll
        for (int q = 0; q < 8; q++) {
            if (rr[q] < 10 && cc[q] < 10 && cc[q] > rr[q]) {
                const float gsc = gv[q] * inv_s[wbase + rr[q]] * inv_s[wbase + cc[q]];
                float s = 1.0f - gsc;
                s = (s <= 0.f) ? 1e-10f : s;
                racc += sqrtf(2.0f * s);
            }
        }
#pragma unroll
        for (int o = 16; o; o >>= 1) racc += __shfl_xor_sync(0xffffffffu, racc, o);
        if (lane == 0) g_regpart[blockIdx.y * 8 + warp] = racc;
    }

    // ---- epilogue: transpose, scale by inv norm, softpool K=10 ----
    float* xs = reinterpret_cast<float*>(dsm);
    float* xw = xs + warp * 640;
    const int cr = lane >> 2, cc2 = 2 * (lane & 3);
#pragma unroll
    for (int mi = 0; mi < 2; mi++) {
#pragma unroll
        for (int jn = 0; jn < 5; jn++) {
            xw[(cr + 0) * 40 + jn * 8 + cc2 + 0] = acc[mi][jn][0];
            xw[(cr + 0) * 40 + jn * 8 + cc2 + 1] = acc[mi][jn][1];
            xw[(cr + 8) * 40 + jn * 8 + cc2 + 0] = acc[mi][jn][2];
            xw[(cr + 8) * 40 + jn * 8 + cc2 + 1] = acc[mi][jn][3];
        }
        __syncwarp();
#pragma unroll
        for (int it = 0; it < 2; it++) {
            const int item = it * 32 + lane;
            const int row = item & 15, cls = item >> 4;
            const float* xp = xw + row * 40 + cls * 10;
            const float* ip = inv_s + warp_n * 40 + cls * 10;
            float x[10];
#pragma unroll
            for (int j = 0; j < 10; j++) x[j] = xp[j] * ip[j];
            float mx = x[0];
#pragma unroll
            for (int j = 1; j < 10; j++) mx = fmaxf(mx, x[j]);
            float s = 0.f, hs = 0.f;
#pragma unroll
            for (int j = 0; j < 10; j++) {
                const float e = __expf(INV_GAMMA * (x[j] - mx));
                s += e; hs += e * x[j];
            }
            const int grow = m0 + warp_m * 32 + mi * 16 + row;
            const int gcls = blockIdx.y * 8 + warp_n * 4 + cls;
            g_h[(size_t)grow * PC + gcls] = hs / s;
        }
        __syncwarp();
    }
}

// ---------------------------------------------------------------------------
// Kernel 2: per-row CE (single pass, 512 threads x 16 logits in registers)
// + fused final reduction by the last block (deterministic fixed-order trees).
// ---------------------------------------------------------------------------
__global__ __launch_bounds__(512) void k_ce_final(const int* __restrict__ labels,
                                                  float* __restrict__ out)
{
    __shared__ float sred[512];
    __shared__ int sflag;
    const int b   = blockIdx.x;
    const int tid = threadIdx.x;
    const float* row = g_h + (size_t)b * PC;
    const int lab = labels[b];

    float v[16];
    float mx = -3.0e38f;
#pragma unroll
    for (int j = 0; j < 16; j++) {
        const int i = tid + 512 * j;
        v[j] = LMD * row[i] - ((i == lab) ? (LMD * MARGIN) : 0.f);
        mx = fmaxf(mx, v[j]);
    }
    sred[tid] = mx; __syncthreads();
    for (int o = 256; o; o >>= 1) {
        if (tid < o) sred[tid] = fmaxf(sred[tid], sred[tid + o]);
        __syncthreads();
    }
    mx = sred[0];
    __syncthreads();

    float s = 0.f;
#pragma unroll
    for (int j = 0; j < 16; j++) s += __expf(v[j] - mx);
    sred[tid] = s; __syncthreads();
    for (int o = 256; o; o >>= 1) {
        if (tid < o) sred[tid] += sred[tid + o];
        __syncthreads();
    }

    if (tid == 0) {
        const float vl = LMD * row[lab] - LMD * MARGIN;
        g_rowloss[b] = -(vl - mx - logf(sred[0]));
        __threadfence();
        const int old = atomicAdd(&g_ctr, 1);
        sflag = (old == PB - 1) ? 1 : 0;
    }
    __syncthreads();
    if (!sflag) return;

    __threadfence();
    sred[tid] = (tid < PB) ? g_rowloss[tid] : 0.f;
    __syncthreads();
    for (int o = 256; o; o >>= 1) {
        if (tid < o) sred[tid] += sred[tid + o];
        __syncthreads();
    }
    const float losssum = sred[0];
    __syncthreads();

    float r = 0.f;
    for (int i = tid; i < PC; i += 512) r += g_regpart[i];
    sred[tid] = r; __syncthreads();
    for (int o = 256; o; o >>= 1) {
        if (tid < o) sred[tid] += sred[tid + o];
        __syncthreads();
    }
    if (tid == 0) {
        const float reg = sred[0] / ((float)PC * (float)(PK * (PK - 1)));
        out[0] = losssum / (float)PB + TAU * reg;
        g_ctr = 0;
    }
}

// ---------------------------------------------------------------------------
typedef CUresult (*EncodeFn)(CUtensorMap*, CUtensorMapDataType, cuuint32_t, void*,
                             const cuuint64_t*, const cuuint64_t*, const cuuint32_t*,
                             const cuuint32_t*, CUtensorMapInterleave, CUtensorMapSwizzle,
                             CUtensorMapL2promotion, CUtensorMapFloatOOBfill);

extern "C" void kernel_launch(void* const* d_in, const int* in_sizes, int n_in,
                              void* d_out, int out_size)
{
    (void)in_sizes; (void)n_in; (void)out_size;
    const float* emb    = (const float*)d_in[0];
    const int*   labels = (const int*)d_in[1];
    const float* fc     = (const float*)d_in[2];
    float*       out    = (float*)d_out;

    void* encode_raw = nullptr;
    cudaDriverEntryPointQueryResult qr;
    cudaGetDriverEntryPoint("cuTensorMapEncodeTiled", &encode_raw, cudaEnableDefault, &qr);
    EncodeFn encode = (EncodeFn)encode_raw;

    void* ebf_dev = nullptr;
    cudaGetSymbolAddress(&ebf_dev, g_ebf);

    CUtensorMap tma_a{}, tma_b{};
    {
        cuuint64_t dims[2]    = {PE, PB};
        cuuint64_t strides[1] = {PE * 2};
        cuuint32_t box[2]     = {KSTAGE, 128};
        cuuint32_t estr[2]    = {1, 1};
        encode(&tma_a, CU_TENSOR_MAP_DATA_TYPE_BFLOAT16, 2, ebf_dev,
               dims, strides, box, estr, CU_TENSOR_MAP_INTERLEAVE_NONE,
               CU_TENSOR_MAP_SWIZZLE_128B, CU_TENSOR_MAP_L2_PROMOTION_L2_128B,
               CU_TENSOR_MAP_FLOAT_OOB_FILL_NONE);
    }
    {
        // fc fp32, SWIZZLE_NONE: box0 = 64 fp32 = 256 B rows
        cuuint64_t dims[2]    = {PE, PN};
        cuuint64_t strides[1] = {PE * 4};
        cuuint32_t box[2]     = {KSTAGE, NBLK};
        cuuint32_t estr[2]    = {1, 1};
        encode(&tma_b, CU_TENSOR_MAP_DATA_TYPE_FLOAT32, 2, (void*)fc,
               dims, strides, box, estr, CU_TENSOR_MAP_INTERLEAVE_NONE,
               CU_TENSOR_MAP_SWIZZLE_NONE, CU_TENSOR_MAP_L2_PROMOTION_L2_128B,
               CU_TENSOR_MAP_FLOAT_OOB_FILL_NONE);
    }

    cudaFuncSetAttribute(k_gemm_mma, cudaFuncAttributeMaxDynamicSharedMemorySize, GSMEM);

    k_prep<<<(PB * PE) / 256, 256>>>(emb);
    k_gemm_mma<<<dim3(PB / 128, PN / NBLK), 256, GSMEM>>>(tma_a, tma_b);
    k_ce_final<<<PB, 512>>>(labels, out);
}